// round 1
// baseline (speedup 1.0000x reference)
#include <cuda_runtime.h>
#include <math_constants.h>

#define N_NODES 50000
#define N_EDGES 1200000
#define N_GRAPHS 512
#define D1 64
#define NF 92
#define NG 50
#define BN_EPS 1e-5f
#define LOG2F_C 0.6931471805599453f

typedef unsigned long long ull;

// -------------------- device scratch (no cudaMalloc allowed) --------------------
__device__ float g_out[N_NODES * D1];   // node features
__device__ float g_h[N_NODES * D1];     // lin1 output (gathered by edges)
__device__ float g_agg[N_NODES * D1];   // scatter-add target
__device__ float g_C[N_EDGES];          // cosine cutoff per edge
__device__ float g_bnstats[2 * D1];     // [sum(64), sumsq(64)]
__device__ float g_pool[N_GRAPHS * D1];
__device__ float g_cnt[N_GRAPHS];

// -------------------- helpers --------------------
__device__ __forceinline__ ull ffma2(ull a, ull b, ull c) {
    ull d;
    asm("fma.rn.f32x2 %0, %1, %2, %3;" : "=l"(d) : "l"(a), "l"(b), "l"(c));
    return d;
}
__device__ __forceinline__ float f2lo(ull v) { return __uint_as_float((unsigned)(v & 0xffffffffull)); }
__device__ __forceinline__ float f2hi(ull v) { return __uint_as_float((unsigned)(v >> 32)); }

__device__ __forceinline__ float sspf(float v) {
    // softplus(v) - log(2), numerically stable
    return fmaxf(v, 0.f) + __logf(1.f + __expf(-fabsf(v))) - LOG2F_C;
}

// =====================================================================
// pre FC: out = relu(x @ pre_W.T + pre_b)   [50000,92] @ [92,64]
// warp-per-node, pre_W staged in smem (stride 93, conflict-free)
// =====================================================================
__global__ __launch_bounds__(256) void k_pre(const float* __restrict__ x,
                                             const float* __restrict__ W,
                                             const float* __restrict__ b) {
    __shared__ float sW[64 * 93];
    int tid = threadIdx.x;
    for (int i = tid; i < 64 * 92; i += 256) {
        int f = i / 92, k = i % 92;
        sW[f * 93 + k] = W[i];
    }
    __syncthreads();
    int lane = tid & 31;
    int warp = (blockIdx.x * blockDim.x + tid) >> 5;
    int nwarps = (gridDim.x * blockDim.x) >> 5;
    float b0 = b[lane], b1 = b[lane + 32];
    for (int n = warp; n < N_NODES; n += nwarps) {
        const float* xr = x + (size_t)n * NF;
        float x0 = xr[lane];
        float x1 = xr[32 + lane];
        float x2 = (lane < 28) ? xr[64 + lane] : 0.f;
        float a0 = b0, a1 = b1;
#pragma unroll
        for (int k = 0; k < NF; k++) {
            float src = (k < 32) ? x0 : ((k < 64) ? x1 : x2);
            float xv = __shfl_sync(0xffffffffu, src, k & 31);
            a0 = fmaf(xv, sW[lane * 93 + k], a0);
            a1 = fmaf(xv, sW[(lane + 32) * 93 + k], a1);
        }
        g_out[(size_t)n * D1 + lane] = fmaxf(a0, 0.f);
        g_out[(size_t)n * D1 + lane + 32] = fmaxf(a1, 0.f);
    }
}

// =====================================================================
// cosine cutoff: C = 0.5*(cos(pi*ew/8)+1)
// =====================================================================
__global__ void k_cutoff(const float* __restrict__ ew) {
    int i = blockIdx.x * blockDim.x + threadIdx.x;
    if (i < N_EDGES) g_C[i] = 0.5f * (cospif(ew[i] * 0.125f) + 1.f);
}

// =====================================================================
// lin1: g_h = g_out @ cf_W1.T   [50000,64] @ [64,64]
// f32x2 tile: 128 nodes/block, 256 threads, 8 nodes x 4 feats per thread
// smem: sWt[64][64] transposed, sA[128][128] A duplicated {v,v}
// =====================================================================
#define LIN1_SMEM ((4096 + 16384) * 4)
__global__ __launch_bounds__(256, 2) void k_lin1(const float* __restrict__ W) {
    extern __shared__ float sm[];
    float* sWt = sm;          // [k][f] = W[f][k]
    float* sA = sm + 4096;    // [e][2k] duplicated

    int tid = threadIdx.x;
    int tx = tid & 15, ty = tid >> 4;
    int n0 = blockIdx.x * 128;

    for (int i = tid; i < 64 * 64; i += 256) {
        int f = i >> 6, k = i & 63;
        sWt[k * 64 + f] = W[i];
    }
    for (int i = tid; i < 128 * 64; i += 256) {
        int e = i >> 6, k = i & 63;
        int n = n0 + e;
        float v = (n < N_NODES) ? g_out[n * D1 + k] : 0.f;
        *(float2*)&sA[e * 128 + 2 * k] = make_float2(v, v);
    }
    __syncthreads();

    ull acc[8][2];
#pragma unroll
    for (int ii = 0; ii < 8; ii++) { acc[ii][0] = 0ull; acc[ii][1] = 0ull; }
#pragma unroll
    for (int p = 0; p < 32; p++) {
        ulonglong2 b0 = *reinterpret_cast<const ulonglong2*>(&sWt[(2 * p) * 64 + 4 * tx]);
        ulonglong2 b1 = *reinterpret_cast<const ulonglong2*>(&sWt[(2 * p + 1) * 64 + 4 * tx]);
#pragma unroll
        for (int ii = 0; ii < 8; ii++) {
            ulonglong2 a = *reinterpret_cast<const ulonglong2*>(&sA[(ty + 16 * ii) * 128 + 4 * p]);
            acc[ii][0] = ffma2(a.x, b0.x, acc[ii][0]);
            acc[ii][1] = ffma2(a.x, b0.y, acc[ii][1]);
            acc[ii][0] = ffma2(a.y, b1.x, acc[ii][0]);
            acc[ii][1] = ffma2(a.y, b1.y, acc[ii][1]);
        }
    }
#pragma unroll
    for (int ii = 0; ii < 8; ii++) {
        int n = n0 + ty + 16 * ii;
        if (n < N_NODES) {
            float4 o;
            o.x = f2lo(acc[ii][0]); o.y = f2hi(acc[ii][0]);
            o.z = f2lo(acc[ii][1]); o.w = f2hi(acc[ii][1]);
            *(float4*)&g_h[n * D1 + 4 * tx] = o;
        }
    }
}

// =====================================================================
// edge kernel (the big one): per edge
//   W = ssp(EA @ W1.T + b1) @ W2.T + b2; W *= C; msg = h[src]*W; agg[dst] += msg
// 128 edges/block, 256 threads, thread = 8 edges x 4 features, f32x2 MACs
// =====================================================================
#define EDGE_SMEM ((3200 + 4096 + 16384 + 64 + 64 + 128 + 128 + 128) * 4)
__global__ __launch_bounds__(256, 2) void k_edge(const float* __restrict__ EA,
                                                 const int* __restrict__ ei,
                                                 const float* __restrict__ W1,
                                                 const float* __restrict__ bias1,
                                                 const float* __restrict__ W2,
                                                 const float* __restrict__ bias2) {
    extern __shared__ float sm[];
    float* sW1t = sm;             // [50][64]
    float* sW2t = sm + 3200;      // [64][64]
    float* sA = sm + 7296;        // phase1: EA dup [128][100]; phase2: hid dup [128][128]
    float* sB1 = sm + 23680;      // [64]
    float* sB2 = sB1 + 64;        // [64]
    float* sC = sB2 + 64;         // [128]
    int* sSrc = (int*)(sC + 128); // [128]
    int* sDst = sSrc + 128;       // [128]

    int tid = threadIdx.x;
    int tx = tid & 15, ty = tid >> 4;
    int e0 = blockIdx.x * 128;

    for (int i = tid; i < 64 * 50; i += 256) {
        int f = i / 50, k = i % 50;
        sW1t[k * 64 + f] = W1[i];
    }
    for (int i = tid; i < 64 * 64; i += 256) {
        int f = i >> 6, k = i & 63;
        sW2t[k * 64 + f] = W2[i];
    }
    if (tid < 64) { sB1[tid] = bias1[tid]; sB2[tid] = bias2[tid]; }
    if (tid >= 64 && tid < 192) {
        int t = tid - 64;
        int e = e0 + t;
        sC[t] = g_C[e];
        sSrc[t] = ei[e];
        sDst[t] = ei[N_EDGES + e];
    }
    for (int i = tid; i < 128 * 50; i += 256) {
        int e = i / 50, k = i % 50;
        float v = EA[(size_t)(e0 + e) * NG + k];
        *(float2*)&sA[e * 100 + 2 * k] = make_float2(v, v);
    }
    __syncthreads();

    // ---- phase 1: hidden = EA @ W1.T, K=50 (25 f32x2 pairs) ----
    ull acc[8][2];
#pragma unroll
    for (int ii = 0; ii < 8; ii++) { acc[ii][0] = 0ull; acc[ii][1] = 0ull; }
#pragma unroll
    for (int p = 0; p < 25; p++) {
        ulonglong2 b0 = *reinterpret_cast<const ulonglong2*>(&sW1t[(2 * p) * 64 + 4 * tx]);
        ulonglong2 b1 = *reinterpret_cast<const ulonglong2*>(&sW1t[(2 * p + 1) * 64 + 4 * tx]);
#pragma unroll
        for (int ii = 0; ii < 8; ii++) {
            ulonglong2 a = *reinterpret_cast<const ulonglong2*>(&sA[(ty + 16 * ii) * 100 + 4 * p]);
            acc[ii][0] = ffma2(a.x, b0.x, acc[ii][0]);
            acc[ii][1] = ffma2(a.x, b0.y, acc[ii][1]);
            acc[ii][0] = ffma2(a.y, b1.x, acc[ii][0]);
            acc[ii][1] = ffma2(a.y, b1.y, acc[ii][1]);
        }
    }
    __syncthreads();   // all phase-1 smem reads complete

    // ---- ssp + store duplicated hidden ----
    float bb0 = sB1[4 * tx + 0], bb1 = sB1[4 * tx + 1];
    float bb2 = sB1[4 * tx + 2], bb3 = sB1[4 * tx + 3];
#pragma unroll
    for (int ii = 0; ii < 8; ii++) {
        int e = ty + 16 * ii;
        float h0 = sspf(f2lo(acc[ii][0]) + bb0);
        float h1 = sspf(f2hi(acc[ii][0]) + bb1);
        float h2 = sspf(f2lo(acc[ii][1]) + bb2);
        float h3 = sspf(f2hi(acc[ii][1]) + bb3);
        float2* p = (float2*)&sA[e * 128 + 8 * tx];
        p[0] = make_float2(h0, h0);
        p[1] = make_float2(h1, h1);
        p[2] = make_float2(h2, h2);
        p[3] = make_float2(h3, h3);
    }
    __syncthreads();

    // ---- phase 2: w = hid @ W2.T, K=64 (32 pairs) ----
    ull wacc[8][2];
#pragma unroll
    for (int ii = 0; ii < 8; ii++) { wacc[ii][0] = 0ull; wacc[ii][1] = 0ull; }
#pragma unroll
    for (int p = 0; p < 32; p++) {
        ulonglong2 b0 = *reinterpret_cast<const ulonglong2*>(&sW2t[(2 * p) * 64 + 4 * tx]);
        ulonglong2 b1 = *reinterpret_cast<const ulonglong2*>(&sW2t[(2 * p + 1) * 64 + 4 * tx]);
#pragma unroll
        for (int ii = 0; ii < 8; ii++) {
            ulonglong2 a = *reinterpret_cast<const ulonglong2*>(&sA[(ty + 16 * ii) * 128 + 4 * p]);
            wacc[ii][0] = ffma2(a.x, b0.x, wacc[ii][0]);
            wacc[ii][1] = ffma2(a.x, b0.y, wacc[ii][1]);
            wacc[ii][0] = ffma2(a.y, b1.x, wacc[ii][0]);
            wacc[ii][1] = ffma2(a.y, b1.y, wacc[ii][1]);
        }
    }

    // ---- phase 3: bias, cutoff, gather h[src], scatter-add agg[dst] ----
    float c0 = sB2[4 * tx + 0], c1 = sB2[4 * tx + 1];
    float c2 = sB2[4 * tx + 2], c3 = sB2[4 * tx + 3];
#pragma unroll
    for (int ii = 0; ii < 8; ii++) {
        int e = ty + 16 * ii;
        float cc = sC[e];
        int sn = sSrc[e], dn = sDst[e];
        float4 hh = *(const float4*)&g_h[sn * D1 + 4 * tx];
        float w0 = (f2lo(wacc[ii][0]) + c0) * cc;
        float w1 = (f2hi(wacc[ii][0]) + c1) * cc;
        float w2 = (f2lo(wacc[ii][1]) + c2) * cc;
        float w3 = (f2hi(wacc[ii][1]) + c3) * cc;
        float* ap = &g_agg[dn * D1 + 4 * tx];
        atomicAdd(ap + 0, w0 * hh.x);
        atomicAdd(ap + 1, w1 * hh.y);
        atomicAdd(ap + 2, w2 * hh.z);
        atomicAdd(ap + 3, w3 * hh.w);
    }
}

// =====================================================================
// node kernel: t = ssp(agg @ cf_W2.T + cf_b2) @ int_W.T + int_b
//              out += t; accumulate BN sum/sumsq per feature
// =====================================================================
#define NODE_SMEM ((4096 + 4096 + 16384 + 64 + 64 + 64 + 64) * 4)
__global__ __launch_bounds__(256, 2) void k_node(const float* __restrict__ Wa,
                                                 const float* __restrict__ ba,
                                                 const float* __restrict__ Wb,
                                                 const float* __restrict__ bb) {
    extern __shared__ float sm[];
    float* sWat = sm;           // [64][64]
    float* sWbt = sm + 4096;    // [64][64]
    float* sA = sm + 8192;      // [128][128] dup (agg, then hid)
    float* sBa = sm + 24576;    // 64
    float* sBb = sBa + 64;      // 64
    float* sSum = sBb + 64;     // 64
    float* sSq = sSum + 64;     // 64

    int tid = threadIdx.x;
    int tx = tid & 15, ty = tid >> 4;
    int n0 = blockIdx.x * 128;

    for (int i = tid; i < 64 * 64; i += 256) {
        int f = i >> 6, k = i & 63;
        sWat[k * 64 + f] = Wa[i];
        sWbt[k * 64 + f] = Wb[i];
    }
    if (tid < 64) { sBa[tid] = ba[tid]; sBb[tid] = bb[tid]; sSum[tid] = 0.f; sSq[tid] = 0.f; }
    for (int i = tid; i < 128 * 64; i += 256) {
        int e = i >> 6, k = i & 63;
        int n = n0 + e;
        float v = (n < N_NODES) ? g_agg[n * D1 + k] : 0.f;
        *(float2*)&sA[e * 128 + 2 * k] = make_float2(v, v);
    }
    __syncthreads();

    ull acc[8][2];
#pragma unroll
    for (int ii = 0; ii < 8; ii++) { acc[ii][0] = 0ull; acc[ii][1] = 0ull; }
#pragma unroll
    for (int p = 0; p < 32; p++) {
        ulonglong2 b0 = *reinterpret_cast<const ulonglong2*>(&sWat[(2 * p) * 64 + 4 * tx]);
        ulonglong2 b1 = *reinterpret_cast<const ulonglong2*>(&sWat[(2 * p + 1) * 64 + 4 * tx]);
#pragma unroll
        for (int ii = 0; ii < 8; ii++) {
            ulonglong2 a = *reinterpret_cast<const ulonglong2*>(&sA[(ty + 16 * ii) * 128 + 4 * p]);
            acc[ii][0] = ffma2(a.x, b0.x, acc[ii][0]);
            acc[ii][1] = ffma2(a.x, b0.y, acc[ii][1]);
            acc[ii][0] = ffma2(a.y, b1.x, acc[ii][0]);
            acc[ii][1] = ffma2(a.y, b1.y, acc[ii][1]);
        }
    }
    __syncthreads();

    float bb0 = sBa[4 * tx + 0], bb1 = sBa[4 * tx + 1];
    float bb2 = sBa[4 * tx + 2], bb3 = sBa[4 * tx + 3];
#pragma unroll
    for (int ii = 0; ii < 8; ii++) {
        int e = ty + 16 * ii;
        float h0 = sspf(f2lo(acc[ii][0]) + bb0);
        float h1 = sspf(f2hi(acc[ii][0]) + bb1);
        float h2 = sspf(f2lo(acc[ii][1]) + bb2);
        float h3 = sspf(f2hi(acc[ii][1]) + bb3);
        float2* p = (float2*)&sA[e * 128 + 8 * tx];
        p[0] = make_float2(h0, h0);
        p[1] = make_float2(h1, h1);
        p[2] = make_float2(h2, h2);
        p[3] = make_float2(h3, h3);
    }
    __syncthreads();

    ull wacc[8][2];
#pragma unroll
    for (int ii = 0; ii < 8; ii++) { wacc[ii][0] = 0ull; wacc[ii][1] = 0ull; }
#pragma unroll
    for (int p = 0; p < 32; p++) {
        ulonglong2 b0 = *reinterpret_cast<const ulonglong2*>(&sWbt[(2 * p) * 64 + 4 * tx]);
        ulonglong2 b1 = *reinterpret_cast<const ulonglong2*>(&sWbt[(2 * p + 1) * 64 + 4 * tx]);
#pragma unroll
        for (int ii = 0; ii < 8; ii++) {
            ulonglong2 a = *reinterpret_cast<const ulonglong2*>(&sA[(ty + 16 * ii) * 128 + 4 * p]);
            wacc[ii][0] = ffma2(a.x, b0.x, wacc[ii][0]);
            wacc[ii][1] = ffma2(a.x, b0.y, wacc[ii][1]);
            wacc[ii][0] = ffma2(a.y, b1.x, wacc[ii][0]);
            wacc[ii][1] = ffma2(a.y, b1.y, wacc[ii][1]);
        }
    }

    float c0 = sBb[4 * tx + 0], c1 = sBb[4 * tx + 1];
    float c2 = sBb[4 * tx + 2], c3 = sBb[4 * tx + 3];
    float ps0 = 0.f, ps1 = 0.f, ps2 = 0.f, ps3 = 0.f;
    float pq0 = 0.f, pq1 = 0.f, pq2 = 0.f, pq3 = 0.f;
#pragma unroll
    for (int ii = 0; ii < 8; ii++) {
        int n = n0 + ty + 16 * ii;
        if (n < N_NODES) {
            float4 prev = *(const float4*)&g_out[n * D1 + 4 * tx];
            float r0 = f2lo(wacc[ii][0]) + c0 + prev.x;
            float r1 = f2hi(wacc[ii][0]) + c1 + prev.y;
            float r2 = f2lo(wacc[ii][1]) + c2 + prev.z;
            float r3 = f2hi(wacc[ii][1]) + c3 + prev.w;
            float4 o; o.x = r0; o.y = r1; o.z = r2; o.w = r3;
            *(float4*)&g_out[n * D1 + 4 * tx] = o;
            ps0 += r0; ps1 += r1; ps2 += r2; ps3 += r3;
            pq0 += r0 * r0; pq1 += r1 * r1; pq2 += r2 * r2; pq3 += r3 * r3;
        }
    }
    atomicAdd(&sSum[4 * tx + 0], ps0); atomicAdd(&sSum[4 * tx + 1], ps1);
    atomicAdd(&sSum[4 * tx + 2], ps2); atomicAdd(&sSum[4 * tx + 3], ps3);
    atomicAdd(&sSq[4 * tx + 0], pq0);  atomicAdd(&sSq[4 * tx + 1], pq1);
    atomicAdd(&sSq[4 * tx + 2], pq2);  atomicAdd(&sSq[4 * tx + 3], pq3);
    __syncthreads();
    if (tid < 64) {
        atomicAdd(&g_bnstats[tid], sSum[tid]);
        atomicAdd(&g_bnstats[64 + tid], sSq[tid]);
    }
}

// =====================================================================
// BN normalize (training-mode batch stats, biased variance)
// =====================================================================
__global__ void k_bn(const float* __restrict__ g, const float* __restrict__ b) {
    int idx = blockIdx.x * blockDim.x + threadIdx.x;
    if (idx >= N_NODES * D1) return;
    int f = idx & 63;
    const float invN = 1.f / (float)N_NODES;
    float mu = g_bnstats[f] * invN;
    float var = fmaxf(g_bnstats[64 + f] * invN - mu * mu, 0.f);
    float sc = rsqrtf(var + BN_EPS) * g[f];
    g_out[idx] = (g_out[idx] - mu) * sc + b[f];
}

// =====================================================================
// global mean pool: per-graph sums + counts via atomics
// =====================================================================
__global__ void k_pool(const int* __restrict__ batch) {
    int idx = blockIdx.x * blockDim.x + threadIdx.x;
    if (idx >= N_NODES * D1) return;
    int n = idx >> 6, f = idx & 63;
    int bg = batch[n];
    atomicAdd(&g_pool[bg * D1 + f], g_out[idx]);
    if (f == 0) atomicAdd(&g_cnt[bg], 1.f);
}

// =====================================================================
// head: pooled mean -> relu(post FC) -> linear out  (one block per graph)
// =====================================================================
__global__ void k_head(const float* __restrict__ postW, const float* __restrict__ postb,
                       const float* __restrict__ outW, const float* __restrict__ outb,
                       float* __restrict__ y) {
    int g = blockIdx.x;
    int f = threadIdx.x;  // 64 threads
    __shared__ float sp[64];
    __shared__ float sr[2];
    float cnt = fmaxf(g_cnt[g], 1.f);
    sp[f] = g_pool[g * D1 + f] / cnt;
    __syncthreads();
    float a = postb[f];
#pragma unroll
    for (int k = 0; k < 64; k++) a = fmaf(sp[k], postW[f * 64 + k], a);
    float hp = fmaxf(a, 0.f) * outW[f];
#pragma unroll
    for (int o = 16; o > 0; o >>= 1) hp += __shfl_down_sync(0xffffffffu, hp, o);
    if ((f & 31) == 0) sr[f >> 5] = hp;
    __syncthreads();
    if (f == 0) y[g] = sr[0] + sr[1] + outb[0];
}

// =====================================================================
extern "C" void kernel_launch(void* const* d_in, const int* in_sizes, int n_in,
                              void* d_out, int out_size) {
    const float* x      = (const float*)d_in[0];
    const float* ew     = (const float*)d_in[1];
    const float* ea     = (const float*)d_in[2];
    const int*   ei     = (const int*)d_in[3];
    const int*   batch  = (const int*)d_in[4];
    const float* pre_W  = (const float*)d_in[5];
    const float* pre_b  = (const float*)d_in[6];
    const float* mlp_W1 = (const float*)d_in[7];
    const float* mlp_b1 = (const float*)d_in[8];
    const float* mlp_W2 = (const float*)d_in[9];
    const float* mlp_b2 = (const float*)d_in[10];
    const float* cf_W1  = (const float*)d_in[11];
    const float* cf_W2  = (const float*)d_in[12];
    const float* cf_b2  = (const float*)d_in[13];
    const float* int_W  = (const float*)d_in[14];
    const float* int_b  = (const float*)d_in[15];
    const float* bn_g   = (const float*)d_in[16];
    const float* bn_b   = (const float*)d_in[17];
    const float* post_W = (const float*)d_in[18];
    const float* post_b = (const float*)d_in[19];
    const float* out_W  = (const float*)d_in[20];
    const float* out_b  = (const float*)d_in[21];
    float* y = (float*)d_out;

    void *agg_p, *bn_p, *pool_p, *cnt_p;
    cudaGetSymbolAddress(&agg_p, g_agg);
    cudaGetSymbolAddress(&bn_p, g_bnstats);
    cudaGetSymbolAddress(&pool_p, g_pool);
    cudaGetSymbolAddress(&cnt_p, g_cnt);

    cudaFuncSetAttribute(k_edge, cudaFuncAttributeMaxDynamicSharedMemorySize, EDGE_SMEM);
    cudaFuncSetAttribute(k_node, cudaFuncAttributeMaxDynamicSharedMemorySize, NODE_SMEM);
    cudaFuncSetAttribute(k_lin1, cudaFuncAttributeMaxDynamicSharedMemorySize, LIN1_SMEM);

    k_pre<<<512, 256>>>(x, pre_W, pre_b);
    k_cutoff<<<(N_EDGES + 255) / 256, 256>>>(ew);
    cudaMemsetAsync(pool_p, 0, N_GRAPHS * D1 * sizeof(float));
    cudaMemsetAsync(cnt_p, 0, N_GRAPHS * sizeof(float));

    for (int l = 0; l < 3; l++) {
        k_lin1<<<(N_NODES + 127) / 128, 256, LIN1_SMEM>>>(cf_W1 + l * 64 * 64);
        cudaMemsetAsync(agg_p, 0, (size_t)N_NODES * D1 * sizeof(float));
        cudaMemsetAsync(bn_p, 0, 2 * D1 * sizeof(float));
        k_edge<<<N_EDGES / 128, 256, EDGE_SMEM>>>(ea, ei,
                                                  mlp_W1 + l * 64 * 50, mlp_b1 + l * 64,
                                                  mlp_W2 + l * 64 * 64, mlp_b2 + l * 64);
        k_node<<<(N_NODES + 127) / 128, 256, NODE_SMEM>>>(cf_W2 + l * 64 * 64, cf_b2 + l * 64,
                                                          int_W + l * 64 * 64, int_b + l * 64);
        k_bn<<<(N_NODES * D1 + 255) / 256, 256>>>(bn_g + l * 64, bn_b + l * 64);
    }

    k_pool<<<(N_NODES * D1 + 255) / 256, 256>>>(batch);
    k_head<<<N_GRAPHS, 64>>>(post_W, post_b, out_W, out_b, y);
}